// round 14
// baseline (speedup 1.0000x reference)
#include <cuda_runtime.h>
#include <cuda_fp16.h>
#include <cstdint>

// Problem constants (fixed shapes)
#define B_SZ     4
#define N_SEQ    4096
#define TOKENS   16384      // B*N
#define DM       1024
#define NH       16
#define HD       64
#define CHUNK    256
#define LBLK     512        // 2*CHUNK
#define QSTR     3072       // fused QKV row stride (halves)

// GEMM tiling (R8 config): CTA 128x128, 8 warps (2x4), warp tile 64x32,
// BK=64, 3 stages, 96KB smem -> 2 CTAs/SM.
#define BM 128
#define BN 128
#define BK 64
#define NSTAGE 3
#define A_BYTES (BM * 128)                 // 16384
#define STG_BYTES (BM * 128 + BN * 128)    // 32768
#define GSMEM (NSTAGE * STG_BYTES)         // 98304
#define NKT (DM / BK)                      // 16

// -------- scratch (device globals: no allocation allowed) --------
__device__ __half g_QKVh[(size_t)TOKENS * 3 * DM]; // fp16 fused QKV
__device__ __half g_Ah[(size_t)TOKENS * DM];       // fp16 attention output
__device__ __half g_Xh[(size_t)TOKENS * DM];       // fp16-rounded input
__device__ __half g_WTh[4 * (size_t)DM * DM];      // fp16 W^T (q,k,v,o)
__device__ float  g_bias[3 * DM];                  // concat bq|bk|bv

// ============================================================================
// helpers
// ============================================================================
__device__ __forceinline__ void cpasync16(uint32_t dst, const void* src) {
    asm volatile("cp.async.cg.shared.global [%0], [%1], 16;\n"
                 :: "r"(dst), "l"(src));
}
#define CP_COMMIT()  asm volatile("cp.async.commit_group;\n")
#define CP_WAIT1()   asm volatile("cp.async.wait_group 1;\n")
#define CP_WAIT0()   asm volatile("cp.async.wait_group 0;\n")

__device__ __forceinline__ uint32_t smem_u32(const void* p) {
    uint32_t a;
    asm("{ .reg .u64 t; cvta.to.shared.u64 t, %1; cvt.u32.u64 %0, t; }"
        : "=r"(a) : "l"(p));
    return a;
}
__device__ __forceinline__ uint32_t sw128(uint32_t off) {
    return off ^ ((off >> 3) & 0x70);
}
__device__ __forceinline__ void mma16816(float* c, const uint32_t* a,
                                         uint32_t b0, uint32_t b1) {
    asm volatile(
        "mma.sync.aligned.m16n8k16.row.col.f32.f16.f16.f32 "
        "{%0,%1,%2,%3}, {%4,%5,%6,%7}, {%8,%9}, {%0,%1,%2,%3};\n"
        : "+f"(c[0]), "+f"(c[1]), "+f"(c[2]), "+f"(c[3])
        : "r"(a[0]), "r"(a[1]), "r"(a[2]), "r"(a[3]), "r"(b0), "r"(b1));
}
__device__ __forceinline__ void ldsm_x4(uint32_t* r, uint32_t addr) {
    asm volatile(
        "ldmatrix.sync.aligned.m8n8.x4.shared.b16 {%0,%1,%2,%3}, [%4];"
        : "=r"(r[0]), "=r"(r[1]), "=r"(r[2]), "=r"(r[3]) : "r"(addr));
}
__device__ __forceinline__ void ldsm_x4_t(uint32_t* r, uint32_t addr) {
    asm volatile(
        "ldmatrix.sync.aligned.m8n8.x4.trans.shared.b16 {%0,%1,%2,%3}, [%4];"
        : "=r"(r[0]), "=r"(r[1]), "=r"(r[2]), "=r"(r[3]) : "r"(addr));
}
__device__ __forceinline__ uint32_t pack2(float a, float b) {
    __half2 h = __floats2half2_rn(a, b);
    return *reinterpret_cast<uint32_t*>(&h);
}
__device__ __forceinline__ uint32_t h2ex2(uint32_t x) {
    uint32_t r;
    asm("ex2.approx.f16x2 %0, %1;" : "=r"(r) : "r"(x));
    return r;
}
__device__ __forceinline__ void store2(float* C, size_t off, float v0, float v1) {
    *reinterpret_cast<float2*>(C + off) = make_float2(v0, v1);
}
__device__ __forceinline__ void store2(__half* C, size_t off, float v0, float v1) {
    __half2 h = __floats2half2_rn(v0, v1);
    *reinterpret_cast<__half2*>(C + off) = h;
}

// ============================================================================
// FP16 mma.sync GEMM (R8 config): C[M,N] = A[M,1024] @ Bt^T + bias
// CTA 128x128, 256 threads, warp tile 64x32, 3 stages, 2 CTAs/SM.
// ============================================================================
template <typename TOut>
__global__ __launch_bounds__(256, 2) void gemm_h(
    const __half* __restrict__ A, const __half* __restrict__ Bt,
    const float* __restrict__ bias, TOut* __restrict__ C, int ldc)
{
    extern __shared__ char smem[];
    const uint32_t sb = smem_u32(smem);
    const int tid  = threadIdx.x;
    const int wid  = tid >> 5;
    const int lane = tid & 31;
    const int lq   = lane >> 2;
    const int lr   = lane & 3;
    const int wrow = (wid & 1) * 64;
    const int wcol = (wid >> 1) * 32;
    const int row0 = blockIdx.y * BM;
    const int col0 = blockIdx.x * BN;

    const int l7   = lane & 7;
    const int aHi  = (lane >> 4) & 1;
    const int bHi  = (lane >> 3) & 1;
    int aRowOff[4], bRowOff[2];
#pragma unroll
    for (int mi = 0; mi < 4; mi++)
        aRowOff[mi] = (wrow + mi * 16 + l7 + ((lane >> 3) & 1) * 8) * 128;
#pragma unroll
    for (int p = 0; p < 2; p++)
        bRowOff[p] = A_BYTES + (wcol + p * 16 + ((lane >> 4) & 1) * 8 + l7) * 128;

    float acc[4][4][4];
#pragma unroll
    for (int mi = 0; mi < 4; mi++)
#pragma unroll
        for (int ni = 0; ni < 4; ni++)
#pragma unroll
            for (int c = 0; c < 4; c++) acc[mi][ni][c] = 0.f;

    auto load_tile = [&](int t, int s) {
        const int k0 = t * BK;
        const uint32_t base = sb + s * STG_BYTES;
#pragma unroll
        for (int u = 0; u < 4; u++) {
            int g = tid + u * 256;
            int r = g >> 3, gc = g & 7;
            cpasync16(base + sw128(r * 128 + gc * 16),
                      &A[(size_t)(row0 + r) * DM + k0 + gc * 8]);
        }
#pragma unroll
        for (int u = 0; u < 4; u++) {
            int g = tid + u * 256;
            int r = g >> 3, gc = g & 7;
            cpasync16(base + A_BYTES + sw128(r * 128 + gc * 16),
                      &Bt[(size_t)(col0 + r) * DM + k0 + gc * 8]);
        }
    };

    load_tile(0, 0); CP_COMMIT();
    load_tile(1, 1); CP_COMMIT();

    for (int t = 0; t < NKT; t++) {
        const int buf = t % NSTAGE;
        CP_WAIT1();
        __syncthreads();

        const uint32_t sAu = sb + buf * STG_BYTES;
#pragma unroll
        for (int ks = 0; ks < 4; ks++) {
            const int gA = (((2 * ks + aHi) ^ l7) << 4);
            const int gB = (((2 * ks + bHi) ^ l7) << 4);
            uint32_t af[4][4];
#pragma unroll
            for (int mi = 0; mi < 4; mi++)
                ldsm_x4(af[mi], sAu + aRowOff[mi] + gA);
            uint32_t bf[2][4];
#pragma unroll
            for (int p = 0; p < 2; p++)
                ldsm_x4(bf[p], sAu + bRowOff[p] + gB);
#pragma unroll
            for (int mi = 0; mi < 4; mi++)
#pragma unroll
                for (int p = 0; p < 2; p++) {
                    mma16816(acc[mi][2 * p],     af[mi], bf[p][0], bf[p][1]);
                    mma16816(acc[mi][2 * p + 1], af[mi], bf[p][2], bf[p][3]);
                }
        }
        // WAR on stage (t+2)%3 == (t-1)%3: protected by top-of-iter barrier.
        if (t + 2 < NKT) load_tile(t + 2, (t + 2) % NSTAGE);
        CP_COMMIT();
    }

#pragma unroll
    for (int mi = 0; mi < 4; mi++) {
        const int r = row0 + wrow + mi * 16 + lq;
#pragma unroll
        for (int ni = 0; ni < 4; ni++) {
            const int c = col0 + wcol + ni * 8 + lr * 2;
            const float b0 = bias[c], b1 = bias[c + 1];
            store2(C, (size_t)r * ldc + c, acc[mi][ni][0] + b0, acc[mi][ni][1] + b1);
            store2(C, (size_t)(r + 8) * ldc + c, acc[mi][ni][2] + b0, acc[mi][ni][3] + b1);
        }
    }
}

// ============================================================================
// Fused prep: round X to fp16 (32B/thread) | transpose 4 weights | bias.
// ============================================================================
#define PREP_RX   8192
#define PREP_TW   (PREP_RX + 4096)
#define PREP_ALL  (PREP_TW + 12)

__global__ __launch_bounds__(256) void prep_all(
    const float* __restrict__ x,
    const float* __restrict__ Wq, const float* __restrict__ Wk,
    const float* __restrict__ Wv, const float* __restrict__ Wo,
    const float* __restrict__ bq, const float* __restrict__ bk,
    const float* __restrict__ bv,
    __half* __restrict__ xh, __half* __restrict__ wth,
    float* __restrict__ bp)
{
    const int b = blockIdx.x;
    if (b < PREP_RX) {
        int i = b * 256 + threadIdx.x;
        float4 v0 = reinterpret_cast<const float4*>(x)[2 * i];
        float4 v1 = reinterpret_cast<const float4*>(x)[2 * i + 1];
        uint4 o;
        o.x = pack2(v0.x, v0.y);
        o.y = pack2(v0.z, v0.w);
        o.z = pack2(v1.x, v1.y);
        o.w = pack2(v1.z, v1.w);
        reinterpret_cast<uint4*>(xh)[i] = o;
    } else if (b < PREP_TW) {
        __shared__ float t[32][33];
        const int bb = b - PREP_RX;
        const int z  = bb >> 10;
        const int bx = (bb & 31) * 32;
        const int by = ((bb >> 5) & 31) * 32;
        const float* W = (z == 0) ? Wq : (z == 1) ? Wk : (z == 2) ? Wv : Wo;
        __half* WT = wth + (size_t)z * DM * DM;
        const int tx = threadIdx.x & 31;
        const int ty = threadIdx.x >> 5;
        const int xg = bx + tx;
#pragma unroll
        for (int j = ty; j < 32; j += 8)
            t[j][tx] = W[(size_t)(by + j) * DM + xg];
        __syncthreads();
        const int xo = by + tx;
#pragma unroll
        for (int j = ty; j < 32; j += 8)
            WT[(size_t)(bx + j) * DM + xo] = __float2half_rn(t[tx][j]);
    } else {
        int i = (b - PREP_TW) * 256 + threadIdx.x;
        float v = (i < DM) ? bq[i] : (i < 2 * DM) ? bk[i - DM] : bv[i - 2 * DM];
        bp[i] = v;
    }
}

// ============================================================================
// FP16 tensor-core flash attention (R13 kernel, per-batch pointers).
// Grid (4, 16, 8): qtile, head, pair. QKV/O pre-offset to the batch base.
// 3-stage KV ring, one barrier per kt iter. 2 CTAs/SM (64KB smem).
// ============================================================================
#define ATT_SMEM 65536
#define AQ_OFF   0
#define AK_OFF(b) (16384 + (b) * 16384)
#define AV_OFF(b) (24576 + (b) * 16384)
#define NKV 8

__global__ __launch_bounds__(256, 2) void attn_h(
    const __half* __restrict__ QKV, const int* __restrict__ layer_bit_p,
    __half* __restrict__ O)
{
    extern __shared__ char smem[];
    const uint32_t sb = smem_u32(smem);
    const int bit  = layer_bit_p[0];
    const int tid  = threadIdx.x;
    const int wid  = tid >> 5;
    const int lane = tid & 31;
    const int lq   = lane >> 2;
    const int lr   = lane & 3;
    const int wrow = wid * 16;
    const int h    = blockIdx.y;
    const int p    = blockIdx.z;           // pair within batch (0..7)
    const int msk  = (1 << bit) - 1;
    const int ac   = ((p >> bit) << (bit + 1)) | (p & msk);
    const int bc   = ac | (1 << bit);

    auto grow = [&](int t) -> size_t {
        int c = (t < CHUNK) ? ac : bc;
        return (size_t)((c << 8) + (t & (CHUNK - 1)));   // token within batch
    };

    const int q0 = blockIdx.x * 128;

    const int l7  = lane & 7;
    const int aHi = (lane >> 4) & 1;
    const int bHi = (lane >> 3) & 1;
    const int aRowOff = (wrow + l7 + ((lane >> 3) & 1) * 8) * 128;
    int kRowOff[4];
#pragma unroll
    for (int pp = 0; pp < 4; pp++)
        kRowOff[pp] = (pp * 16 + ((lane >> 4) & 1) * 8 + l7) * 128;

#pragma unroll
    for (int u = 0; u < 4; u++) {
        int idx = tid + u * 256;
        int r = idx >> 3, g = idx & 7;
        cpasync16(sb + AQ_OFF + sw128(r * 128 + g * 16),
                  &QKV[grow(q0 + r) * QSTR + h * HD + g * 8]);
    }
    auto load_kv = [&](int kt, int b) {
#pragma unroll
        for (int u = 0; u < 2; u++) {
            int idx = tid + u * 256;
            int r = idx >> 3, g = idx & 7;
            size_t tok = grow(kt * 64 + r);
            cpasync16(sb + AK_OFF(b) + sw128(r * 128 + g * 16),
                      &QKV[tok * QSTR + DM + h * HD + g * 8]);
            cpasync16(sb + AV_OFF(b) + sw128(r * 128 + g * 16),
                      &QKV[tok * QSTR + 2 * DM + h * HD + g * 8]);
        }
    };
    load_kv(0, 0); CP_COMMIT();
    load_kv(1, 1); CP_COMMIT();

    float m0 = -1e30f, m1 = -1e30f, l0 = 0.f, l1 = 0.f;
    float accO[8][4];
#pragma unroll
    for (int d = 0; d < 8; d++)
#pragma unroll
        for (int c = 0; c < 4; c++) accO[d][c] = 0.f;
    uint32_t qf[4][4];

    const float c2 = 0.1803368801111702f;   // (1/8) * log2(e)
    const uint32_t ONES = 0x3C003C00u;
    const int vm = lane >> 3;
    const int vrow_b = (lane & 7) + (vm & 1) * 8;

    for (int kt = 0; kt < NKV; kt++) {
        const int buf = kt % 3;
        CP_WAIT1();
        __syncthreads();

        if (kt == 0) {
#pragma unroll
            for (int ks = 0; ks < 4; ks++) {
                const int gA = (((2 * ks + aHi) ^ l7) << 4);
                ldsm_x4(qf[ks], sb + AQ_OFF + aRowOff + gA);
            }
        }

        const uint32_t sKu = sb + AK_OFF(buf);
        const uint32_t vbase = sb + AV_OFF(buf);

        float s[8][4];
#pragma unroll
        for (int nt = 0; nt < 8; nt++)
#pragma unroll
            for (int c = 0; c < 4; c++) s[nt][c] = 0.f;
#pragma unroll
        for (int ks = 0; ks < 4; ks++) {
            const int gB = (((2 * ks + bHi) ^ l7) << 4);
#pragma unroll
            for (int pp = 0; pp < 4; pp++) {
                uint32_t bf[4];
                ldsm_x4(bf, sKu + kRowOff[pp] + gB);
                mma16816(s[2 * pp],     qf[ks], bf[0], bf[1]);
                mma16816(s[2 * pp + 1], qf[ks], bf[2], bf[3]);
            }
        }

        float mx0 = -1e30f, mx1 = -1e30f;
#pragma unroll
        for (int nt = 0; nt < 8; nt++) {
            s[nt][0] *= c2; s[nt][1] *= c2;
            s[nt][2] *= c2; s[nt][3] *= c2;
            mx0 = fmaxf(mx0, fmaxf(s[nt][0], s[nt][1]));
            mx1 = fmaxf(mx1, fmaxf(s[nt][2], s[nt][3]));
        }
        mx0 = fmaxf(mx0, __shfl_xor_sync(0xffffffffu, mx0, 1));
        mx0 = fmaxf(mx0, __shfl_xor_sync(0xffffffffu, mx0, 2));
        mx1 = fmaxf(mx1, __shfl_xor_sync(0xffffffffu, mx1, 1));
        mx1 = fmaxf(mx1, __shfl_xor_sync(0xffffffffu, mx1, 2));
        const float mn0 = fmaxf(m0, mx0), mn1 = fmaxf(m1, mx1);
        const float fac0 = exp2f(m0 - mn0), fac1 = exp2f(m1 - mn1);
        m0 = mn0; m1 = mn1;

        uint32_t ph[8][2];
#pragma unroll
        for (int nt = 0; nt < 8; nt++) {
            ph[nt][0] = h2ex2(pack2(s[nt][0] - mn0, s[nt][1] - mn0));
            ph[nt][1] = h2ex2(pack2(s[nt][2] - mn1, s[nt][3] - mn1));
        }

#pragma unroll
        for (int dt = 0; dt < 8; dt++) {
            accO[dt][0] *= fac0; accO[dt][1] *= fac0;
            accO[dt][2] *= fac1; accO[dt][3] *= fac1;
        }

        float lacc[4] = {0.f, 0.f, 0.f, 0.f};
#pragma unroll
        for (int kk = 0; kk < 4; kk++) {
            uint32_t pa[4] = {ph[2 * kk][0], ph[2 * kk][1],
                              ph[2 * kk + 1][0], ph[2 * kk + 1][1]};
            mma16816(lacc, pa, ONES, ONES);
            const int vrow = kk * 16 + vrow_b;
#pragma unroll
            for (int dg = 0; dg < 4; dg++) {
                const int gran = (dg * 2 + (vm >> 1)) ^ (lane & 7);
                uint32_t vf[4];
                ldsm_x4_t(vf, vbase + vrow * 128 + gran * 16);
                mma16816(accO[dg * 2],     pa, vf[0], vf[1]);
                mma16816(accO[dg * 2 + 1], pa, vf[2], vf[3]);
            }
        }
        l0 = l0 * fac0 + lacc[0];
        l1 = l1 * fac1 + lacc[2];

        if (kt + 2 < NKV) load_kv(kt + 2, (kt + 2) % 3);
        CP_COMMIT();
    }

    {
        __half2* stage = reinterpret_cast<__half2*>(smem + AQ_OFF);
        const float inv0 = 1.f / l0, inv1 = 1.f / l1;
#pragma unroll
        for (int dt = 0; dt < 8; dt++) {
            stage[(wrow + lq) * 32 + dt * 4 + lr] =
                __floats2half2_rn(accO[dt][0] * inv0, accO[dt][1] * inv0);
            stage[(wrow + lq + 8) * 32 + dt * 4 + lr] =
                __floats2half2_rn(accO[dt][2] * inv1, accO[dt][3] * inv1);
        }
    }
    __syncthreads();
#pragma unroll
    for (int u = 0; u < 4; u++) {
        int idx = tid + u * 256;
        int r = idx >> 3, g = idx & 7;
        uint4 v = *reinterpret_cast<const uint4*>(smem + AQ_OFF + r * 128 + g * 16);
        *reinterpret_cast<uint4*>(&O[grow(q0 + r) * DM + h * HD + g * 8]) = v;
    }
}

// ============================================================================
// Launch: batch-pipelined fork/join (attention on side stream).
// ============================================================================
extern "C" void kernel_launch(void* const* d_in, const int* in_sizes, int n_in,
                              void* d_out, int out_size)
{
    const float* x  = (const float*)d_in[0];
    const float* Wq = (const float*)d_in[1];
    const float* bq = (const float*)d_in[2];
    const float* Wk = (const float*)d_in[3];
    const float* bk = (const float*)d_in[4];
    const float* Wv = (const float*)d_in[5];
    const float* bv = (const float*)d_in[6];
    const float* Wo = (const float*)d_in[7];
    const float* bo = (const float*)d_in[8];
    const int* layer_bit = (const int*)d_in[9];
    float* out = (float*)d_out;

    float* bp;
    __half *qkvh, *ah, *xh, *wth;
    cudaGetSymbolAddress((void**)&qkvh, g_QKVh);
    cudaGetSymbolAddress((void**)&ah, g_Ah);
    cudaGetSymbolAddress((void**)&xh, g_Xh);
    cudaGetSymbolAddress((void**)&wth, g_WTh);
    cudaGetSymbolAddress((void**)&bp, g_bias);
    __half* wto = wth + 3 * (size_t)DM * DM;

    // one-time stream/event creation (host-side resources only)
    static cudaStream_t s1 = [] {
        cudaStream_t s;
        cudaStreamCreateWithFlags(&s, cudaStreamNonBlocking);
        return s;
    }();
    static cudaEvent_t* evs = [] {
        static cudaEvent_t e[8];
        for (int i = 0; i < 8; i++)
            cudaEventCreateWithFlags(&e[i], cudaEventDisableTiming);
        return e;
    }();
    cudaEvent_t* evQ = evs;       // [0..3]
    cudaEvent_t* evA = evs + 4;   // [4..7]

    cudaFuncSetAttribute(gemm_h<__half>,
                         cudaFuncAttributeMaxDynamicSharedMemorySize, GSMEM);
    cudaFuncSetAttribute(gemm_h<float>,
                         cudaFuncAttributeMaxDynamicSharedMemorySize, GSMEM);
    cudaFuncSetAttribute(attn_h,
                         cudaFuncAttributeMaxDynamicSharedMemorySize, ATT_SMEM);

    // prep (main stream)
    prep_all<<<PREP_ALL, 256>>>(x, Wq, Wk, Wv, Wo, bq, bk, bv, xh, wth, bp);

    const size_t xrow = (size_t)N_SEQ * DM;      // tokens per batch * DM
    const size_t qrow = (size_t)N_SEQ * QSTR;

    // QKV per batch on main stream; attention per batch on s1
    dim3 qgrid(3 * DM / BN, N_SEQ / BM);         // (24, 32)
    dim3 agrid(LBLK / 128, NH, 8);               // (4, 16, 8 pairs)
    for (int b = 0; b < B_SZ; b++) {
        gemm_h<__half><<<qgrid, 256, GSMEM>>>(
            xh + b * xrow, wth, bp, qkvh + b * qrow, QSTR);
        cudaEventRecord(evQ[b], 0);
        cudaStreamWaitEvent(s1, evQ[b], 0);
        attn_h<<<agrid, 256, ATT_SMEM, s1>>>(
            qkvh + b * qrow, layer_bit, ah + b * xrow);
        cudaEventRecord(evA[b], s1);
    }

    // O-proj per batch on main stream, gated on that batch's attention
    dim3 ogrid(DM / BN, N_SEQ / BM);             // (8, 32)
    for (int b = 0; b < B_SZ; b++) {
        cudaStreamWaitEvent(0, evA[b], 0);
        gemm_h<float><<<ogrid, 256, GSMEM>>>(
            ah + b * xrow, wto, bo, out + b * xrow, DM);
    }
}

// round 15
// speedup vs baseline: 1.0513x; 1.0513x over previous
#include <cuda_runtime.h>
#include <cuda_fp16.h>
#include <cstdint>

// Problem constants (fixed shapes)
#define B_SZ     4
#define N_SEQ    4096
#define TOKENS   16384      // B*N
#define DM       1024
#define NH       16
#define HD       64
#define CHUNK    256
#define LBLK     512        // 2*CHUNK
#define QSTR     3072       // fused QKV row stride (halves)

// GEMM tiling (R8 config): CTA 128x128, 8 warps (2x4), warp tile 64x32,
// BK=64, 3 stages, 96KB smem -> 2 CTAs/SM.
#define BM 128
#define BN 128
#define BK 64
#define NSTAGE 3
#define A_BYTES (BM * 128)                 // 16384
#define STG_BYTES (BM * 128 + BN * 128)    // 32768
#define GSMEM (NSTAGE * STG_BYTES)         // 98304
#define NKT (DM / BK)                      // 16

// -------- scratch (device globals: no allocation allowed) --------
__device__ __half g_QKVh[(size_t)TOKENS * 3 * DM]; // fp16 fused QKV
__device__ __half g_Ah[(size_t)TOKENS * DM];       // fp16 attention output
__device__ __half g_Xh[(size_t)TOKENS * DM];       // fp16-rounded input
__device__ __half g_WTh[4 * (size_t)DM * DM];      // fp16 W^T (q,k,v,o)
__device__ float  g_bias[3 * DM];                  // concat bq|bk|bv

// ============================================================================
// helpers
// ============================================================================
__device__ __forceinline__ void cpasync16(uint32_t dst, const void* src) {
    asm volatile("cp.async.cg.shared.global [%0], [%1], 16;\n"
                 :: "r"(dst), "l"(src));
}
#define CP_COMMIT()  asm volatile("cp.async.commit_group;\n")
#define CP_WAIT1()   asm volatile("cp.async.wait_group 1;\n")
#define CP_WAIT0()   asm volatile("cp.async.wait_group 0;\n")

__device__ __forceinline__ uint32_t smem_u32(const void* p) {
    uint32_t a;
    asm("{ .reg .u64 t; cvta.to.shared.u64 t, %1; cvt.u32.u64 %0, t; }"
        : "=r"(a) : "l"(p));
    return a;
}
__device__ __forceinline__ uint32_t sw128(uint32_t off) {
    return off ^ ((off >> 3) & 0x70);
}
__device__ __forceinline__ void mma16816(float* c, const uint32_t* a,
                                         uint32_t b0, uint32_t b1) {
    asm volatile(
        "mma.sync.aligned.m16n8k16.row.col.f32.f16.f16.f32 "
        "{%0,%1,%2,%3}, {%4,%5,%6,%7}, {%8,%9}, {%0,%1,%2,%3};\n"
        : "+f"(c[0]), "+f"(c[1]), "+f"(c[2]), "+f"(c[3])
        : "r"(a[0]), "r"(a[1]), "r"(a[2]), "r"(a[3]), "r"(b0), "r"(b1));
}
__device__ __forceinline__ void ldsm_x4(uint32_t* r, uint32_t addr) {
    asm volatile(
        "ldmatrix.sync.aligned.m8n8.x4.shared.b16 {%0,%1,%2,%3}, [%4];"
        : "=r"(r[0]), "=r"(r[1]), "=r"(r[2]), "=r"(r[3]) : "r"(addr));
}
__device__ __forceinline__ void ldsm_x4_t(uint32_t* r, uint32_t addr) {
    asm volatile(
        "ldmatrix.sync.aligned.m8n8.x4.trans.shared.b16 {%0,%1,%2,%3}, [%4];"
        : "=r"(r[0]), "=r"(r[1]), "=r"(r[2]), "=r"(r[3]) : "r"(addr));
}
__device__ __forceinline__ uint32_t pack2(float a, float b) {
    __half2 h = __floats2half2_rn(a, b);
    return *reinterpret_cast<uint32_t*>(&h);
}
__device__ __forceinline__ uint32_t h2ex2(uint32_t x) {
    uint32_t r;
    asm("ex2.approx.f16x2 %0, %1;" : "=r"(r) : "r"(x));
    return r;
}
__device__ __forceinline__ void store2(float* C, size_t off, float v0, float v1) {
    *reinterpret_cast<float2*>(C + off) = make_float2(v0, v1);
}
__device__ __forceinline__ void store2(__half* C, size_t off, float v0, float v1) {
    __half2 h = __floats2half2_rn(v0, v1);
    *reinterpret_cast<__half2*>(C + off) = h;
}

// ============================================================================
// FP16 mma.sync GEMM (R8 config): C[M,N] = A[M,1024] @ Bt^T + bias
// CTA 128x128, 256 threads, warp tile 64x32, 3 stages, 2 CTAs/SM.
// ============================================================================
template <typename TOut>
__global__ __launch_bounds__(256, 2) void gemm_h(
    const __half* __restrict__ A, const __half* __restrict__ Bt,
    const float* __restrict__ bias, TOut* __restrict__ C, int ldc)
{
    extern __shared__ char smem[];
    const uint32_t sb = smem_u32(smem);
    const int tid  = threadIdx.x;
    const int wid  = tid >> 5;
    const int lane = tid & 31;
    const int lq   = lane >> 2;
    const int lr   = lane & 3;
    const int wrow = (wid & 1) * 64;
    const int wcol = (wid >> 1) * 32;
    const int row0 = blockIdx.y * BM;
    const int col0 = blockIdx.x * BN;

    const int l7   = lane & 7;
    const int aHi  = (lane >> 4) & 1;
    const int bHi  = (lane >> 3) & 1;
    int aRowOff[4], bRowOff[2];
#pragma unroll
    for (int mi = 0; mi < 4; mi++)
        aRowOff[mi] = (wrow + mi * 16 + l7 + ((lane >> 3) & 1) * 8) * 128;
#pragma unroll
    for (int p = 0; p < 2; p++)
        bRowOff[p] = A_BYTES + (wcol + p * 16 + ((lane >> 4) & 1) * 8 + l7) * 128;

    float acc[4][4][4];
#pragma unroll
    for (int mi = 0; mi < 4; mi++)
#pragma unroll
        for (int ni = 0; ni < 4; ni++)
#pragma unroll
            for (int c = 0; c < 4; c++) acc[mi][ni][c] = 0.f;

    auto load_tile = [&](int t, int s) {
        const int k0 = t * BK;
        const uint32_t base = sb + s * STG_BYTES;
#pragma unroll
        for (int u = 0; u < 4; u++) {
            int g = tid + u * 256;
            int r = g >> 3, gc = g & 7;
            cpasync16(base + sw128(r * 128 + gc * 16),
                      &A[(size_t)(row0 + r) * DM + k0 + gc * 8]);
        }
#pragma unroll
        for (int u = 0; u < 4; u++) {
            int g = tid + u * 256;
            int r = g >> 3, gc = g & 7;
            cpasync16(base + A_BYTES + sw128(r * 128 + gc * 16),
                      &Bt[(size_t)(col0 + r) * DM + k0 + gc * 8]);
        }
    };

    load_tile(0, 0); CP_COMMIT();
    load_tile(1, 1); CP_COMMIT();

    for (int t = 0; t < NKT; t++) {
        const int buf = t % NSTAGE;
        CP_WAIT1();
        __syncthreads();

        const uint32_t sAu = sb + buf * STG_BYTES;
#pragma unroll
        for (int ks = 0; ks < 4; ks++) {
            const int gA = (((2 * ks + aHi) ^ l7) << 4);
            const int gB = (((2 * ks + bHi) ^ l7) << 4);
            uint32_t af[4][4];
#pragma unroll
            for (int mi = 0; mi < 4; mi++)
                ldsm_x4(af[mi], sAu + aRowOff[mi] + gA);
            uint32_t bf[2][4];
#pragma unroll
            for (int p = 0; p < 2; p++)
                ldsm_x4(bf[p], sAu + bRowOff[p] + gB);
#pragma unroll
            for (int mi = 0; mi < 4; mi++)
#pragma unroll
                for (int p = 0; p < 2; p++) {
                    mma16816(acc[mi][2 * p],     af[mi], bf[p][0], bf[p][1]);
                    mma16816(acc[mi][2 * p + 1], af[mi], bf[p][2], bf[p][3]);
                }
        }
        // WAR on stage (t+2)%3 == (t-1)%3: protected by top-of-iter barrier.
        if (t + 2 < NKT) load_tile(t + 2, (t + 2) % NSTAGE);
        CP_COMMIT();
    }

#pragma unroll
    for (int mi = 0; mi < 4; mi++) {
        const int r = row0 + wrow + mi * 16 + lq;
#pragma unroll
        for (int ni = 0; ni < 4; ni++) {
            const int c = col0 + wcol + ni * 8 + lr * 2;
            const float b0 = bias[c], b1 = bias[c + 1];
            store2(C, (size_t)r * ldc + c, acc[mi][ni][0] + b0, acc[mi][ni][1] + b1);
            store2(C, (size_t)(r + 8) * ldc + c, acc[mi][ni][2] + b0, acc[mi][ni][3] + b1);
        }
    }
}

// ============================================================================
// Fused prep: round X to fp16 (32B/thread) | transpose 4 weights | bias.
// ============================================================================
#define PREP_RX   8192
#define PREP_TW   (PREP_RX + 4096)
#define PREP_ALL  (PREP_TW + 12)

__global__ __launch_bounds__(256) void prep_all(
    const float* __restrict__ x,
    const float* __restrict__ Wq, const float* __restrict__ Wk,
    const float* __restrict__ Wv, const float* __restrict__ Wo,
    const float* __restrict__ bq, const float* __restrict__ bk,
    const float* __restrict__ bv,
    __half* __restrict__ xh, __half* __restrict__ wth,
    float* __restrict__ bp)
{
    const int b = blockIdx.x;
    if (b < PREP_RX) {
        int i = b * 256 + threadIdx.x;
        float4 v0 = reinterpret_cast<const float4*>(x)[2 * i];
        float4 v1 = reinterpret_cast<const float4*>(x)[2 * i + 1];
        uint4 o;
        o.x = pack2(v0.x, v0.y);
        o.y = pack2(v0.z, v0.w);
        o.z = pack2(v1.x, v1.y);
        o.w = pack2(v1.z, v1.w);
        reinterpret_cast<uint4*>(xh)[i] = o;
    } else if (b < PREP_TW) {
        __shared__ float t[32][33];
        const int bb = b - PREP_RX;
        const int z  = bb >> 10;
        const int bx = (bb & 31) * 32;
        const int by = ((bb >> 5) & 31) * 32;
        const float* W = (z == 0) ? Wq : (z == 1) ? Wk : (z == 2) ? Wv : Wo;
        __half* WT = wth + (size_t)z * DM * DM;
        const int tx = threadIdx.x & 31;
        const int ty = threadIdx.x >> 5;
        const int xg = bx + tx;
#pragma unroll
        for (int j = ty; j < 32; j += 8)
            t[j][tx] = W[(size_t)(by + j) * DM + xg];
        __syncthreads();
        const int xo = by + tx;
#pragma unroll
        for (int j = ty; j < 32; j += 8)
            WT[(size_t)(bx + j) * DM + xo] = __float2half_rn(t[tx][j]);
    } else {
        int i = (b - PREP_TW) * 256 + threadIdx.x;
        float v = (i < DM) ? bq[i] : (i < 2 * DM) ? bk[i - DM] : bv[i - 2 * DM];
        bp[i] = v;
    }
}

// ============================================================================
// FP16 tensor-core flash attention (R13 body; half-base pointers).
// Grid (4, 16, 16): qtile, head, z = bloc*8 + pair (bloc = batch within half).
// 3-stage KV ring, one barrier per kt iter. 2 CTAs/SM (64KB smem).
// ============================================================================
#define ATT_SMEM 65536
#define AQ_OFF   0
#define AK_OFF(b) (16384 + (b) * 16384)
#define AV_OFF(b) (24576 + (b) * 16384)
#define NKV 8

__global__ __launch_bounds__(256, 2) void attn_h(
    const __half* __restrict__ QKV, const int* __restrict__ layer_bit_p,
    __half* __restrict__ O)
{
    extern __shared__ char smem[];
    const uint32_t sb = smem_u32(smem);
    const int bit  = layer_bit_p[0];
    const int tid  = threadIdx.x;
    const int wid  = tid >> 5;
    const int lane = tid & 31;
    const int lq   = lane >> 2;
    const int lr   = lane & 3;
    const int wrow = wid * 16;
    const int h    = blockIdx.y;
    const int bloc = blockIdx.z >> 3;      // batch within half (0/1)
    const int p    = blockIdx.z & 7;       // pair within batch
    const int msk  = (1 << bit) - 1;
    const int ac   = ((p >> bit) << (bit + 1)) | (p & msk);
    const int bc   = ac | (1 << bit);

    auto grow = [&](int t) -> size_t {
        int c = (t < CHUNK) ? ac : bc;
        return (size_t)bloc * N_SEQ + ((c << 8) + (t & (CHUNK - 1)));
    };

    const int q0 = blockIdx.x * 128;

    const int l7  = lane & 7;
    const int aHi = (lane >> 4) & 1;
    const int bHi = (lane >> 3) & 1;
    const int aRowOff = (wrow + l7 + ((lane >> 3) & 1) * 8) * 128;
    int kRowOff[4];
#pragma unroll
    for (int pp = 0; pp < 4; pp++)
        kRowOff[pp] = (pp * 16 + ((lane >> 4) & 1) * 8 + l7) * 128;

#pragma unroll
    for (int u = 0; u < 4; u++) {
        int idx = tid + u * 256;
        int r = idx >> 3, g = idx & 7;
        cpasync16(sb + AQ_OFF + sw128(r * 128 + g * 16),
                  &QKV[grow(q0 + r) * QSTR + h * HD + g * 8]);
    }
    auto load_kv = [&](int kt, int b) {
#pragma unroll
        for (int u = 0; u < 2; u++) {
            int idx = tid + u * 256;
            int r = idx >> 3, g = idx & 7;
            size_t tok = grow(kt * 64 + r);
            cpasync16(sb + AK_OFF(b) + sw128(r * 128 + g * 16),
                      &QKV[tok * QSTR + DM + h * HD + g * 8]);
            cpasync16(sb + AV_OFF(b) + sw128(r * 128 + g * 16),
                      &QKV[tok * QSTR + 2 * DM + h * HD + g * 8]);
        }
    };
    load_kv(0, 0); CP_COMMIT();
    load_kv(1, 1); CP_COMMIT();

    float m0 = -1e30f, m1 = -1e30f, l0 = 0.f, l1 = 0.f;
    float accO[8][4];
#pragma unroll
    for (int d = 0; d < 8; d++)
#pragma unroll
        for (int c = 0; c < 4; c++) accO[d][c] = 0.f;
    uint32_t qf[4][4];

    const float c2 = 0.1803368801111702f;   // (1/8) * log2(e)
    const uint32_t ONES = 0x3C003C00u;
    const int vm = lane >> 3;
    const int vrow_b = (lane & 7) + (vm & 1) * 8;

    for (int kt = 0; kt < NKV; kt++) {
        const int buf = kt % 3;
        CP_WAIT1();
        __syncthreads();

        if (kt == 0) {
#pragma unroll
            for (int ks = 0; ks < 4; ks++) {
                const int gA = (((2 * ks + aHi) ^ l7) << 4);
                ldsm_x4(qf[ks], sb + AQ_OFF + aRowOff + gA);
            }
        }

        const uint32_t sKu = sb + AK_OFF(buf);
        const uint32_t vbase = sb + AV_OFF(buf);

        float s[8][4];
#pragma unroll
        for (int nt = 0; nt < 8; nt++)
#pragma unroll
            for (int c = 0; c < 4; c++) s[nt][c] = 0.f;
#pragma unroll
        for (int ks = 0; ks < 4; ks++) {
            const int gB = (((2 * ks + bHi) ^ l7) << 4);
#pragma unroll
            for (int pp = 0; pp < 4; pp++) {
                uint32_t bf[4];
                ldsm_x4(bf, sKu + kRowOff[pp] + gB);
                mma16816(s[2 * pp],     qf[ks], bf[0], bf[1]);
                mma16816(s[2 * pp + 1], qf[ks], bf[2], bf[3]);
            }
        }

        float mx0 = -1e30f, mx1 = -1e30f;
#pragma unroll
        for (int nt = 0; nt < 8; nt++) {
            s[nt][0] *= c2; s[nt][1] *= c2;
            s[nt][2] *= c2; s[nt][3] *= c2;
            mx0 = fmaxf(mx0, fmaxf(s[nt][0], s[nt][1]));
            mx1 = fmaxf(mx1, fmaxf(s[nt][2], s[nt][3]));
        }
        mx0 = fmaxf(mx0, __shfl_xor_sync(0xffffffffu, mx0, 1));
        mx0 = fmaxf(mx0, __shfl_xor_sync(0xffffffffu, mx0, 2));
        mx1 = fmaxf(mx1, __shfl_xor_sync(0xffffffffu, mx1, 1));
        mx1 = fmaxf(mx1, __shfl_xor_sync(0xffffffffu, mx1, 2));
        const float mn0 = fmaxf(m0, mx0), mn1 = fmaxf(m1, mx1);
        const float fac0 = exp2f(m0 - mn0), fac1 = exp2f(m1 - mn1);
        m0 = mn0; m1 = mn1;

        uint32_t ph[8][2];
#pragma unroll
        for (int nt = 0; nt < 8; nt++) {
            ph[nt][0] = h2ex2(pack2(s[nt][0] - mn0, s[nt][1] - mn0));
            ph[nt][1] = h2ex2(pack2(s[nt][2] - mn1, s[nt][3] - mn1));
        }

#pragma unroll
        for (int dt = 0; dt < 8; dt++) {
            accO[dt][0] *= fac0; accO[dt][1] *= fac0;
            accO[dt][2] *= fac1; accO[dt][3] *= fac1;
        }

        float lacc[4] = {0.f, 0.f, 0.f, 0.f};
#pragma unroll
        for (int kk = 0; kk < 4; kk++) {
            uint32_t pa[4] = {ph[2 * kk][0], ph[2 * kk][1],
                              ph[2 * kk + 1][0], ph[2 * kk + 1][1]};
            mma16816(lacc, pa, ONES, ONES);
            const int vrow = kk * 16 + vrow_b;
#pragma unroll
            for (int dg = 0; dg < 4; dg++) {
                const int gran = (dg * 2 + (vm >> 1)) ^ (lane & 7);
                uint32_t vf[4];
                ldsm_x4_t(vf, vbase + vrow * 128 + gran * 16);
                mma16816(accO[dg * 2],     pa, vf[0], vf[1]);
                mma16816(accO[dg * 2 + 1], pa, vf[2], vf[3]);
            }
        }
        l0 = l0 * fac0 + lacc[0];
        l1 = l1 * fac1 + lacc[2];

        if (kt + 2 < NKV) load_kv(kt + 2, (kt + 2) % 3);
        CP_COMMIT();
    }

    {
        __half2* stage = reinterpret_cast<__half2*>(smem + AQ_OFF);
        const float inv0 = 1.f / l0, inv1 = 1.f / l1;
#pragma unroll
        for (int dt = 0; dt < 8; dt++) {
            stage[(wrow + lq) * 32 + dt * 4 + lr] =
                __floats2half2_rn(accO[dt][0] * inv0, accO[dt][1] * inv0);
            stage[(wrow + lq + 8) * 32 + dt * 4 + lr] =
                __floats2half2_rn(accO[dt][2] * inv1, accO[dt][3] * inv1);
        }
    }
    __syncthreads();
#pragma unroll
    for (int u = 0; u < 4; u++) {
        int idx = tid + u * 256;
        int r = idx >> 3, g = idx & 7;
        uint4 v = *reinterpret_cast<const uint4*>(smem + AQ_OFF + r * 128 + g * 16);
        *reinterpret_cast<uint4*>(&O[grow(q0 + r) * DM + h * HD + g * 8]) = v;
    }
}

// ============================================================================
// Launch: 2-way pipelined fork/join (attention halves on side stream).
//   prep -> QKV_h0 -> [QKV_h1 || attn_h0] -> [O_h0 || attn_h1] -> O_h1
// ============================================================================
extern "C" void kernel_launch(void* const* d_in, const int* in_sizes, int n_in,
                              void* d_out, int out_size)
{
    const float* x  = (const float*)d_in[0];
    const float* Wq = (const float*)d_in[1];
    const float* bq = (const float*)d_in[2];
    const float* Wk = (const float*)d_in[3];
    const float* bk = (const float*)d_in[4];
    const float* Wv = (const float*)d_in[5];
    const float* bv = (const float*)d_in[6];
    const float* Wo = (const float*)d_in[7];
    const float* bo = (const float*)d_in[8];
    const int* layer_bit = (const int*)d_in[9];
    float* out = (float*)d_out;

    float* bp;
    __half *qkvh, *ah, *xh, *wth;
    cudaGetSymbolAddress((void**)&qkvh, g_QKVh);
    cudaGetSymbolAddress((void**)&ah, g_Ah);
    cudaGetSymbolAddress((void**)&xh, g_Xh);
    cudaGetSymbolAddress((void**)&wth, g_WTh);
    cudaGetSymbolAddress((void**)&bp, g_bias);
    __half* wto = wth + 3 * (size_t)DM * DM;

    static cudaStream_t s1 = [] {
        cudaStream_t s;
        cudaStreamCreateWithFlags(&s, cudaStreamNonBlocking);
        return s;
    }();
    static cudaEvent_t* evs = [] {
        static cudaEvent_t e[4];
        for (int i = 0; i < 4; i++)
            cudaEventCreateWithFlags(&e[i], cudaEventDisableTiming);
        return e;
    }();
    cudaEvent_t* evQ = evs;       // [0..1]
    cudaEvent_t* evA = evs + 2;   // [2..3]

    cudaFuncSetAttribute(gemm_h<__half>,
                         cudaFuncAttributeMaxDynamicSharedMemorySize, GSMEM);
    cudaFuncSetAttribute(gemm_h<float>,
                         cudaFuncAttributeMaxDynamicSharedMemorySize, GSMEM);
    cudaFuncSetAttribute(attn_h,
                         cudaFuncAttributeMaxDynamicSharedMemorySize, ATT_SMEM);

    prep_all<<<PREP_ALL, 256>>>(x, Wq, Wk, Wv, Wo, bq, bk, bv, xh, wth, bp);

    const size_t xhalf = (size_t)2 * N_SEQ * DM;     // 8192 tokens * DM
    const size_t qhalf = (size_t)2 * N_SEQ * QSTR;

    dim3 qgrid(3 * DM / BN, (TOKENS / 2) / BM);      // (24, 64)
    dim3 agrid(LBLK / 128, NH, 16);                  // (4, 16, 16)
    dim3 ogrid(DM / BN, (TOKENS / 2) / BM);          // (8, 64)

    for (int hlf = 0; hlf < 2; hlf++) {
        gemm_h<__half><<<qgrid, 256, GSMEM>>>(
            xh + hlf * xhalf, wth, bp, qkvh + hlf * qhalf, QSTR);
        cudaEventRecord(evQ[hlf], 0);
        cudaStreamWaitEvent(s1, evQ[hlf], 0);
        attn_h<<<agrid, 256, ATT_SMEM, s1>>>(
            qkvh + hlf * qhalf, layer_bit, ah + hlf * xhalf);
        cudaEventRecord(evA[hlf], s1);
    }
    for (int hlf = 0; hlf < 2; hlf++) {
        cudaStreamWaitEvent(0, evA[hlf], 0);
        gemm_h<float><<<ogrid, 256, GSMEM>>>(
            ah + hlf * xhalf, wto, bo, out + hlf * xhalf, DM);
    }
}

// round 16
// speedup vs baseline: 1.1418x; 1.0861x over previous
#include <cuda_runtime.h>
#include <cuda_fp16.h>
#include <cstdint>

// Problem constants (fixed shapes)
#define B_SZ     4
#define N_SEQ    4096
#define TOKENS   16384      // B*N
#define DM       1024
#define NH       16
#define HD       64
#define CHUNK    256
#define LBLK     512        // 2*CHUNK
#define QSTR     3072       // fused QKV row stride (halves)

// GEMM tiling (R8 config): CTA 128x128, 8 warps (2x4), warp tile 64x32,
// BK=64, 3 stages, 96KB smem -> 2 CTAs/SM.
#define BM 128
#define BN 128
#define BK 64
#define NSTAGE 3
#define A_BYTES (BM * 128)                 // 16384
#define STG_BYTES (BM * 128 + BN * 128)    // 32768
#define GSMEM (NSTAGE * STG_BYTES)         // 98304
#define NKT (DM / BK)                      // 16

// -------- scratch (device globals: no allocation allowed) --------
__device__ __half g_QKVh[(size_t)TOKENS * 3 * DM]; // fp16 fused QKV
__device__ __half g_Ah[(size_t)TOKENS * DM];       // fp16 attention output
__device__ __half g_Xh[(size_t)TOKENS * DM];       // fp16-rounded input
__device__ __half g_WTh[4 * (size_t)DM * DM];      // fp16 W^T (q,k,v,o)
__device__ float  g_bias[3 * DM];                  // concat bq|bk|bv

// ============================================================================
// helpers
// ============================================================================
__device__ __forceinline__ void cpasync16(uint32_t dst, const void* src) {
    asm volatile("cp.async.cg.shared.global [%0], [%1], 16;\n"
                 :: "r"(dst), "l"(src));
}
#define CP_COMMIT()  asm volatile("cp.async.commit_group;\n")
#define CP_WAIT1()   asm volatile("cp.async.wait_group 1;\n")
#define CP_WAIT0()   asm volatile("cp.async.wait_group 0;\n")

__device__ __forceinline__ uint32_t smem_u32(const void* p) {
    uint32_t a;
    asm("{ .reg .u64 t; cvta.to.shared.u64 t, %1; cvt.u32.u64 %0, t; }"
        : "=r"(a) : "l"(p));
    return a;
}
__device__ __forceinline__ uint32_t sw128(uint32_t off) {
    return off ^ ((off >> 3) & 0x70);
}
__device__ __forceinline__ void mma16816(float* c, const uint32_t* a,
                                         uint32_t b0, uint32_t b1) {
    asm volatile(
        "mma.sync.aligned.m16n8k16.row.col.f32.f16.f16.f32 "
        "{%0,%1,%2,%3}, {%4,%5,%6,%7}, {%8,%9}, {%0,%1,%2,%3};\n"
        : "+f"(c[0]), "+f"(c[1]), "+f"(c[2]), "+f"(c[3])
        : "r"(a[0]), "r"(a[1]), "r"(a[2]), "r"(a[3]), "r"(b0), "r"(b1));
}
__device__ __forceinline__ void ldsm_x4(uint32_t* r, uint32_t addr) {
    asm volatile(
        "ldmatrix.sync.aligned.m8n8.x4.shared.b16 {%0,%1,%2,%3}, [%4];"
        : "=r"(r[0]), "=r"(r[1]), "=r"(r[2]), "=r"(r[3]) : "r"(addr));
}
__device__ __forceinline__ void ldsm_x4_t(uint32_t* r, uint32_t addr) {
    asm volatile(
        "ldmatrix.sync.aligned.m8n8.x4.trans.shared.b16 {%0,%1,%2,%3}, [%4];"
        : "=r"(r[0]), "=r"(r[1]), "=r"(r[2]), "=r"(r[3]) : "r"(addr));
}
__device__ __forceinline__ uint32_t pack2(float a, float b) {
    __half2 h = __floats2half2_rn(a, b);
    return *reinterpret_cast<uint32_t*>(&h);
}
__device__ __forceinline__ uint32_t h2ex2(uint32_t x) {
    uint32_t r;
    asm("ex2.approx.f16x2 %0, %1;" : "=r"(r) : "r"(x));
    return r;
}
__device__ __forceinline__ void store2(float* C, size_t off, float v0, float v1) {
    *reinterpret_cast<float2*>(C + off) = make_float2(v0, v1);
}
__device__ __forceinline__ void store2(__half* C, size_t off, float v0, float v1) {
    __half2 h = __floats2half2_rn(v0, v1);
    *reinterpret_cast<__half2*>(C + off) = h;
}

// ============================================================================
// FP16 mma.sync GEMM (R8 config): C[M,N] = A[M,1024] @ Bt^T + bias
// CTA 128x128, 256 threads, warp tile 64x32, 3 stages, 2 CTAs/SM.
// ============================================================================
template <typename TOut>
__global__ __launch_bounds__(256, 2) void gemm_h(
    const __half* __restrict__ A, const __half* __restrict__ Bt,
    const float* __restrict__ bias, TOut* __restrict__ C, int ldc)
{
    extern __shared__ char smem[];
    const uint32_t sb = smem_u32(smem);
    const int tid  = threadIdx.x;
    const int wid  = tid >> 5;
    const int lane = tid & 31;
    const int lq   = lane >> 2;
    const int lr   = lane & 3;
    const int wrow = (wid & 1) * 64;
    const int wcol = (wid >> 1) * 32;
    const int row0 = blockIdx.y * BM;
    const int col0 = blockIdx.x * BN;

    const int l7   = lane & 7;
    const int aHi  = (lane >> 4) & 1;
    const int bHi  = (lane >> 3) & 1;
    int aRowOff[4], bRowOff[2];
#pragma unroll
    for (int mi = 0; mi < 4; mi++)
        aRowOff[mi] = (wrow + mi * 16 + l7 + ((lane >> 3) & 1) * 8) * 128;
#pragma unroll
    for (int p = 0; p < 2; p++)
        bRowOff[p] = A_BYTES + (wcol + p * 16 + ((lane >> 4) & 1) * 8 + l7) * 128;

    float acc[4][4][4];
#pragma unroll
    for (int mi = 0; mi < 4; mi++)
#pragma unroll
        for (int ni = 0; ni < 4; ni++)
#pragma unroll
            for (int c = 0; c < 4; c++) acc[mi][ni][c] = 0.f;

    auto load_tile = [&](int t, int s) {
        const int k0 = t * BK;
        const uint32_t base = sb + s * STG_BYTES;
#pragma unroll
        for (int u = 0; u < 4; u++) {
            int g = tid + u * 256;
            int r = g >> 3, gc = g & 7;
            cpasync16(base + sw128(r * 128 + gc * 16),
                      &A[(size_t)(row0 + r) * DM + k0 + gc * 8]);
        }
#pragma unroll
        for (int u = 0; u < 4; u++) {
            int g = tid + u * 256;
            int r = g >> 3, gc = g & 7;
            cpasync16(base + A_BYTES + sw128(r * 128 + gc * 16),
                      &Bt[(size_t)(col0 + r) * DM + k0 + gc * 8]);
        }
    };

    load_tile(0, 0); CP_COMMIT();
    load_tile(1, 1); CP_COMMIT();

    for (int t = 0; t < NKT; t++) {
        const int buf = t % NSTAGE;
        CP_WAIT1();
        __syncthreads();

        const uint32_t sAu = sb + buf * STG_BYTES;
#pragma unroll
        for (int ks = 0; ks < 4; ks++) {
            const int gA = (((2 * ks + aHi) ^ l7) << 4);
            const int gB = (((2 * ks + bHi) ^ l7) << 4);
            uint32_t af[4][4];
#pragma unroll
            for (int mi = 0; mi < 4; mi++)
                ldsm_x4(af[mi], sAu + aRowOff[mi] + gA);
            uint32_t bf[2][4];
#pragma unroll
            for (int p = 0; p < 2; p++)
                ldsm_x4(bf[p], sAu + bRowOff[p] + gB);
#pragma unroll
            for (int mi = 0; mi < 4; mi++)
#pragma unroll
                for (int p = 0; p < 2; p++) {
                    mma16816(acc[mi][2 * p],     af[mi], bf[p][0], bf[p][1]);
                    mma16816(acc[mi][2 * p + 1], af[mi], bf[p][2], bf[p][3]);
                }
        }
        // WAR on stage (t+2)%3 == (t-1)%3: protected by top-of-iter barrier.
        if (t + 2 < NKT) load_tile(t + 2, (t + 2) % NSTAGE);
        CP_COMMIT();
    }

#pragma unroll
    for (int mi = 0; mi < 4; mi++) {
        const int r = row0 + wrow + mi * 16 + lq;
#pragma unroll
        for (int ni = 0; ni < 4; ni++) {
            const int c = col0 + wcol + ni * 8 + lr * 2;
            const float b0 = bias[c], b1 = bias[c + 1];
            store2(C, (size_t)r * ldc + c, acc[mi][ni][0] + b0, acc[mi][ni][1] + b1);
            store2(C, (size_t)(r + 8) * ldc + c, acc[mi][ni][2] + b0, acc[mi][ni][3] + b1);
        }
    }
}

// ============================================================================
// Fused prep: round X to fp16 (32B/thread) | transpose 4 weights | bias.
// ============================================================================
#define PREP_RX   8192
#define PREP_TW   (PREP_RX + 4096)
#define PREP_ALL  (PREP_TW + 12)

__global__ __launch_bounds__(256) void prep_all(
    const float* __restrict__ x,
    const float* __restrict__ Wq, const float* __restrict__ Wk,
    const float* __restrict__ Wv, const float* __restrict__ Wo,
    const float* __restrict__ bq, const float* __restrict__ bk,
    const float* __restrict__ bv,
    __half* __restrict__ xh, __half* __restrict__ wth,
    float* __restrict__ bp)
{
    const int b = blockIdx.x;
    if (b < PREP_RX) {
        int i = b * 256 + threadIdx.x;
        float4 v0 = reinterpret_cast<const float4*>(x)[2 * i];
        float4 v1 = reinterpret_cast<const float4*>(x)[2 * i + 1];
        uint4 o;
        o.x = pack2(v0.x, v0.y);
        o.y = pack2(v0.z, v0.w);
        o.z = pack2(v1.x, v1.y);
        o.w = pack2(v1.z, v1.w);
        reinterpret_cast<uint4*>(xh)[i] = o;
    } else if (b < PREP_TW) {
        __shared__ float t[32][33];
        const int bb = b - PREP_RX;
        const int z  = bb >> 10;
        const int bx = (bb & 31) * 32;
        const int by = ((bb >> 5) & 31) * 32;
        const float* W = (z == 0) ? Wq : (z == 1) ? Wk : (z == 2) ? Wv : Wo;
        __half* WT = wth + (size_t)z * DM * DM;
        const int tx = threadIdx.x & 31;
        const int ty = threadIdx.x >> 5;
        const int xg = bx + tx;
#pragma unroll
        for (int j = ty; j < 32; j += 8)
            t[j][tx] = W[(size_t)(by + j) * DM + xg];
        __syncthreads();
        const int xo = by + tx;
#pragma unroll
        for (int j = ty; j < 32; j += 8)
            WT[(size_t)(bx + j) * DM + xo] = __float2half_rn(t[tx][j]);
    } else {
        int i = (b - PREP_TW) * 256 + threadIdx.x;
        float v = (i < DM) ? bq[i] : (i < 2 * DM) ? bk[i - DM] : bv[i - 2 * DM];
        bp[i] = v;
    }
}

// ============================================================================
// FP16 tensor-core flash attention (R13 + fma-folded softmax scale +
// swizzled output staging). Grid (4, 16, 32). 256 threads, 2 CTAs/SM.
// ============================================================================
#define ATT_SMEM 65536
#define AQ_OFF   0
#define AK_OFF(b) (16384 + (b) * 16384)
#define AV_OFF(b) (24576 + (b) * 16384)
#define NKV 8

__global__ __launch_bounds__(256, 2) void attn_h(
    const __half* __restrict__ QKV, const int* __restrict__ layer_bit_p,
    __half* __restrict__ O)
{
    extern __shared__ char smem[];
    const uint32_t sb = smem_u32(smem);
    const int bit  = layer_bit_p[0];
    const int tid  = threadIdx.x;
    const int wid  = tid >> 5;
    const int lane = tid & 31;
    const int lq   = lane >> 2;
    const int lr   = lane & 3;
    const int wrow = wid * 16;
    const int h    = blockIdx.y;
    const int p    = blockIdx.z >> 2;
    const int bb   = blockIdx.z & 3;
    const int msk  = (1 << bit) - 1;
    const int ac   = ((p >> bit) << (bit + 1)) | (p & msk);
    const int bc   = ac | (1 << bit);

    auto grow = [&](int t) -> size_t {
        int c = (t < CHUNK) ? ac : bc;
        int n = (c << 8) + (t & (CHUNK - 1));
        return (size_t)bb * N_SEQ + n;
    };

    const int q0 = blockIdx.x * 128;

    const int l7  = lane & 7;
    const int aHi = (lane >> 4) & 1;
    const int bHi = (lane >> 3) & 1;
    const int aRowOff = (wrow + l7 + ((lane >> 3) & 1) * 8) * 128;
    int kRowOff[4];
#pragma unroll
    for (int pp = 0; pp < 4; pp++)
        kRowOff[pp] = (pp * 16 + ((lane >> 4) & 1) * 8 + l7) * 128;

#pragma unroll
    for (int u = 0; u < 4; u++) {
        int idx = tid + u * 256;
        int r = idx >> 3, g = idx & 7;
        cpasync16(sb + AQ_OFF + sw128(r * 128 + g * 16),
                  &QKV[grow(q0 + r) * QSTR + h * HD + g * 8]);
    }
    auto load_kv = [&](int kt, int b) {
#pragma unroll
        for (int u = 0; u < 2; u++) {
            int idx = tid + u * 256;
            int r = idx >> 3, g = idx & 7;
            size_t tok = grow(kt * 64 + r);
            cpasync16(sb + AK_OFF(b) + sw128(r * 128 + g * 16),
                      &QKV[tok * QSTR + DM + h * HD + g * 8]);
            cpasync16(sb + AV_OFF(b) + sw128(r * 128 + g * 16),
                      &QKV[tok * QSTR + 2 * DM + h * HD + g * 8]);
        }
    };
    load_kv(0, 0); CP_COMMIT();
    load_kv(1, 1); CP_COMMIT();

    float m0 = -1e30f, m1 = -1e30f, l0 = 0.f, l1 = 0.f;
    float accO[8][4];
#pragma unroll
    for (int d = 0; d < 8; d++)
#pragma unroll
        for (int c = 0; c < 4; c++) accO[d][c] = 0.f;
    uint32_t qf[4][4];

    const float c2 = 0.1803368801111702f;   // (1/8) * log2(e)
    const uint32_t ONES = 0x3C003C00u;
    const int vm = lane >> 3;
    const int vrow_b = (lane & 7) + (vm & 1) * 8;

    for (int kt = 0; kt < NKV; kt++) {
        const int buf = kt % 3;
        CP_WAIT1();
        __syncthreads();

        if (kt == 0) {
#pragma unroll
            for (int ks = 0; ks < 4; ks++) {
                const int gA = (((2 * ks + aHi) ^ l7) << 4);
                ldsm_x4(qf[ks], sb + AQ_OFF + aRowOff + gA);
            }
        }

        const uint32_t sKu = sb + AK_OFF(buf);
        const uint32_t vbase = sb + AV_OFF(buf);

        // S = Q K^T  (warp: 16q x 64k, raw logits)
        float s[8][4];
#pragma unroll
        for (int nt = 0; nt < 8; nt++)
#pragma unroll
            for (int c = 0; c < 4; c++) s[nt][c] = 0.f;
#pragma unroll
        for (int ks = 0; ks < 4; ks++) {
            const int gB = (((2 * ks + bHi) ^ l7) << 4);
#pragma unroll
            for (int pp = 0; pp < 4; pp++) {
                uint32_t bf[4];
                ldsm_x4(bf, sKu + kRowOff[pp] + gB);
                mma16816(s[2 * pp],     qf[ks], bf[0], bf[1]);
                mma16816(s[2 * pp + 1], qf[ks], bf[2], bf[3]);
            }
        }

        // online softmax, base-2 domain; max over RAW s, scale folded via fma
        float mx0 = -1e30f, mx1 = -1e30f;
#pragma unroll
        for (int nt = 0; nt < 8; nt++) {
            mx0 = fmaxf(mx0, fmaxf(s[nt][0], s[nt][1]));
            mx1 = fmaxf(mx1, fmaxf(s[nt][2], s[nt][3]));
        }
        mx0 = fmaxf(mx0, __shfl_xor_sync(0xffffffffu, mx0, 1));
        mx0 = fmaxf(mx0, __shfl_xor_sync(0xffffffffu, mx0, 2));
        mx1 = fmaxf(mx1, __shfl_xor_sync(0xffffffffu, mx1, 1));
        mx1 = fmaxf(mx1, __shfl_xor_sync(0xffffffffu, mx1, 2));
        const float mn0 = fmaxf(m0, mx0 * c2), mn1 = fmaxf(m1, mx1 * c2);
        const float fac0 = exp2f(m0 - mn0), fac1 = exp2f(m1 - mn1);
        m0 = mn0; m1 = mn1;

        // p = 2^(c2*s - m) via fma + packed half2 ex2
        uint32_t ph[8][2];
#pragma unroll
        for (int nt = 0; nt < 8; nt++) {
            ph[nt][0] = h2ex2(pack2(fmaf(s[nt][0], c2, -mn0),
                                    fmaf(s[nt][1], c2, -mn0)));
            ph[nt][1] = h2ex2(pack2(fmaf(s[nt][2], c2, -mn1),
                                    fmaf(s[nt][3], c2, -mn1)));
        }

#pragma unroll
        for (int dt = 0; dt < 8; dt++) {
            accO[dt][0] *= fac0; accO[dt][1] *= fac0;
            accO[dt][2] *= fac1; accO[dt][3] *= fac1;
        }

        // O += P @ V, l += P @ 1
        float lacc[4] = {0.f, 0.f, 0.f, 0.f};
#pragma unroll
        for (int kk = 0; kk < 4; kk++) {
            uint32_t pa[4] = {ph[2 * kk][0], ph[2 * kk][1],
                              ph[2 * kk + 1][0], ph[2 * kk + 1][1]};
            mma16816(lacc, pa, ONES, ONES);
            const int vrow = kk * 16 + vrow_b;
#pragma unroll
            for (int dg = 0; dg < 4; dg++) {
                const int gran = (dg * 2 + (vm >> 1)) ^ (lane & 7);
                uint32_t vf[4];
                ldsm_x4_t(vf, vbase + vrow * 128 + gran * 16);
                mma16816(accO[dg * 2],     pa, vf[0], vf[1]);
                mma16816(accO[dg * 2 + 1], pa, vf[2], vf[3]);
            }
        }
        l0 = l0 * fac0 + lacc[0];
        l1 = l1 * fac1 + lacc[2];

        if (kt + 2 < NKV) load_kv(kt + 2, (kt + 2) % 3);
        CP_COMMIT();
    }

    // stage normalized output, SW128-swizzled (conflict-free STS)
    {
        char* stage = smem + AQ_OFF;
        const float inv0 = 1.f / l0, inv1 = 1.f / l1;
#pragma unroll
        for (int dt = 0; dt < 8; dt++) {
            uint32_t o0 = pack2(accO[dt][0] * inv0, accO[dt][1] * inv0);
            uint32_t o1 = pack2(accO[dt][2] * inv1, accO[dt][3] * inv1);
            *reinterpret_cast<uint32_t*>(
                stage + sw128((wrow + lq) * 128 + dt * 16 + lr * 4)) = o0;
            *reinterpret_cast<uint32_t*>(
                stage + sw128((wrow + lq + 8) * 128 + dt * 16 + lr * 4)) = o1;
        }
    }
    __syncthreads();
#pragma unroll
    for (int u = 0; u < 4; u++) {
        int idx = tid + u * 256;
        int r = idx >> 3, g = idx & 7;
        uint4 v = *reinterpret_cast<const uint4*>(
            smem + AQ_OFF + sw128(r * 128 + g * 16));
        *reinterpret_cast<uint4*>(&O[grow(q0 + r) * DM + h * HD + g * 8]) = v;
    }
}

// ============================================================================
// Launch (serial R13 schedule)
// ============================================================================
extern "C" void kernel_launch(void* const* d_in, const int* in_sizes, int n_in,
                              void* d_out, int out_size)
{
    const float* x  = (const float*)d_in[0];
    const float* Wq = (const float*)d_in[1];
    const float* bq = (const float*)d_in[2];
    const float* Wk = (const float*)d_in[3];
    const float* bk = (const float*)d_in[4];
    const float* Wv = (const float*)d_in[5];
    const float* bv = (const float*)d_in[6];
    const float* Wo = (const float*)d_in[7];
    const float* bo = (const float*)d_in[8];
    const int* layer_bit = (const int*)d_in[9];
    float* out = (float*)d_out;

    float* bp;
    __half *qkvh, *ah, *xh, *wth;
    cudaGetSymbolAddress((void**)&qkvh, g_QKVh);
    cudaGetSymbolAddress((void**)&ah, g_Ah);
    cudaGetSymbolAddress((void**)&xh, g_Xh);
    cudaGetSymbolAddress((void**)&wth, g_WTh);
    cudaGetSymbolAddress((void**)&bp, g_bias);
    __half* wto = wth + 3 * (size_t)DM * DM;

    cudaFuncSetAttribute(gemm_h<__half>,
                         cudaFuncAttributeMaxDynamicSharedMemorySize, GSMEM);
    cudaFuncSetAttribute(gemm_h<float>,
                         cudaFuncAttributeMaxDynamicSharedMemorySize, GSMEM);
    cudaFuncSetAttribute(attn_h,
                         cudaFuncAttributeMaxDynamicSharedMemorySize, ATT_SMEM);

    // fused prep (1 launch)
    prep_all<<<PREP_ALL, 256>>>(x, Wq, Wk, Wv, Wo, bq, bk, bv, xh, wth, bp);

    // fused QKV: [16384,1024] @ [1024,3072] -> fp16 QKV (ldc=3072)
    dim3 qgrid(3 * DM / BN, TOKENS / BM);   // (24, 128)
    gemm_h<__half><<<qgrid, 256, GSMEM>>>(xh, wth, bp, qkvh, QSTR);

    // attention
    dim3 agrid(LBLK / 128, NH, (TOKENS / CHUNK) / 2);  // (4, 16, 32)
    attn_h<<<agrid, 256, ATT_SMEM>>>(qkvh, layer_bit, ah);

    // O-proj: [16384,1024] @ [1024,1024] -> f32 out
    dim3 ogrid(DM / BN, TOKENS / BM);       // (8, 128)
    gemm_h<float><<<ogrid, 256, GSMEM>>>(ah, wto, bo, out, DM);
}